// round 14
// baseline (speedup 1.0000x reference)
#include <cuda_runtime.h>
#include <cuda_bf16.h>
#include <cstdint>
#include <math.h>

#define BB 8
#define TT 256
#define DD 1024
#define HH 512
#define SS 32896      // T*(T+1)/2 = 32*1028
#define K_TOP 512
#define NUM_GOLD 10
#define NEGF (-1e20f)

#define M_TOT (BB * TT)   // 2048
#define SLICE 1028        // SS / 32
#define FRB 256           // tail block count (32 per batch)

// ---------------- scratch (no allocation allowed) ----------------
__device__ float d_hs[M_TOT * HH];              // 4 MB
__device__ float d_he[M_TOT * HH];              // 4 MB
__device__ unsigned d_keys[BB * SS];            // ~1 MB radix keys
__device__ int   d_topidx[BB * K_TOP];
__device__ float d_toplog[BB * K_TOP];
__device__ float d_losspart[BB];

__device__ unsigned d_hist0[BB][2048];          // 11-bit pass (from score)
__device__ unsigned d_hist1[BB][2048];          // 11-bit pass
__device__ unsigned d_hist2[BB][1024];          // 10-bit pass
__device__ int d_suff[FRB][1025];
__device__ int d_cgHi[FRB];
__device__ unsigned d_batchdone[BB];
__device__ unsigned d_done;
__device__ unsigned d_barctr[BB];

__device__ __nv_bfloat16 d_Xh[M_TOT * DD];      // 4 MB
__device__ __nv_bfloat16 d_Xl[M_TOT * DD];      // 4 MB
__device__ __nv_bfloat16 d_Wth[2][HH * DD];     // W^T hi, [n,k]
__device__ __nv_bfloat16 d_Wtl[2][HH * DD];     // W^T lo, [n,k]

// ======================= helpers ============================
__device__ __forceinline__ uint32_t smem_u32(const void* p)
{
    uint32_t a;
    asm("{ .reg .u64 t; cvta.to.shared.u64 t, %1; cvt.u32.u64 %0, t; }"
        : "=r"(a) : "l"(p));
    return a;
}

#define LDSM_X4(r0, r1, r2, r3, addr) \
    asm volatile("ldmatrix.sync.aligned.m8n8.x4.shared.b16 {%0,%1,%2,%3}, [%4];" \
                 : "=r"(r0), "=r"(r1), "=r"(r2), "=r"(r3) : "r"(addr))

#define MMA16816(d, a0, a1, a2, a3, b0, b1) \
    asm volatile("mma.sync.aligned.m16n8k16.row.col.f32.bf16.bf16.f32 " \
                 "{%0,%1,%2,%3}, {%4,%5,%6,%7}, {%8,%9}, {%0,%1,%2,%3};" \
                 : "+f"((d)[0]), "+f"((d)[1]), "+f"((d)[2]), "+f"((d)[3]) \
                 : "r"(a0), "r"(a1), "r"(a2), "r"(a3), "r"(b0), "r"(b1))

#define CP_ASYNC16(saddr, gaddr) \
    asm volatile("cp.async.cg.shared.global [%0], [%1], 16;" \
                 :: "r"(saddr), "l"(gaddr))
#define CP_COMMIT()  asm volatile("cp.async.commit_group;" ::: "memory")
#define CP_WAIT1()   asm volatile("cp.async.wait_group 1;" ::: "memory")
#define CP_WAIT0()   asm volatile("cp.async.wait_group 0;" ::: "memory")

// per-batch software grid barrier — BOUNDED spin (latent bug => garbage,
// not a dead container).  32 blocks per batch, all co-resident.
__device__ __forceinline__ void batch_barrier(int b, unsigned target)
{
    __syncthreads();
    if (threadIdx.x == 0) {
        __threadfence();
        atomicAdd(&d_barctr[b], 1u);
        for (int it = 0; it < 10000000; it++) {
            if (*(volatile unsigned*)&d_barctr[b] >= target) break;
        }
        __threadfence();
    }
    __syncthreads();
}

// =================================================================
// Fused conversion: X split (blocks 0..2047) + W transpose/split
// + cross-launch state zeroing.
// =================================================================
__global__ void __launch_bounds__(256)
fused_convert_kernel(const float* __restrict__ X,
                     const float* __restrict__ Ws, const float* __restrict__ We)
{
    const int tid = threadIdx.x;
    if (blockIdx.x < 2048) {
        int i = blockIdx.x * 256 + tid;          // float4 index
        float4 v = ((const float4*)X)[i];
        __nv_bfloat16 h0 = __float2bfloat16_rn(v.x);
        __nv_bfloat16 h1 = __float2bfloat16_rn(v.y);
        __nv_bfloat16 h2 = __float2bfloat16_rn(v.z);
        __nv_bfloat16 h3 = __float2bfloat16_rn(v.w);
        __nv_bfloat16 l0 = __float2bfloat16_rn(v.x - __bfloat162float(h0));
        __nv_bfloat16 l1 = __float2bfloat16_rn(v.y - __bfloat162float(h1));
        __nv_bfloat16 l2 = __float2bfloat16_rn(v.z - __bfloat162float(h2));
        __nv_bfloat16 l3 = __float2bfloat16_rn(v.w - __bfloat162float(h3));
        ((__nv_bfloat162*)d_Xh)[2 * i]     = __nv_bfloat162(h0, h1);
        ((__nv_bfloat162*)d_Xh)[2 * i + 1] = __nv_bfloat162(h2, h3);
        ((__nv_bfloat162*)d_Xl)[2 * i]     = __nv_bfloat162(l0, l1);
        ((__nv_bfloat162*)d_Xl)[2 * i + 1] = __nv_bfloat162(l2, l3);
        return;
    }

    const int wb = blockIdx.x - 2048;            // 0..1023
    if (wb == 0) {
        unsigned* h0p = (unsigned*)d_hist0;
        unsigned* h1p = (unsigned*)d_hist1;
        unsigned* h2p = (unsigned*)d_hist2;
        for (int i = tid; i < BB * 2048; i += 256) { h0p[i] = 0u; h1p[i] = 0u; }
        for (int i = tid; i < BB * 1024; i += 256) h2p[i] = 0u;
        if (tid < BB) { d_batchdone[tid] = 0u; d_barctr[tid] = 0u; }
        if (tid == 0) d_done = 0u;
    }
    const int z = wb >> 9;                       // 0/1
    const int rem = wb & 511;
    const int n0 = (rem & 15) * 32;              // 16 n-tiles
    const int k0 = (rem >> 4) * 32;              // 32 k-tiles

    const float* W = z ? We : Ws;
    __nv_bfloat16* oh = d_Wth[z];
    __nv_bfloat16* ol = d_Wtl[z];

    __shared__ float s[32][33];
    const int tx = tid & 31, ty = tid >> 5;      // 32x8

    for (int j = ty; j < 32; j += 8)
        s[j][tx] = W[(size_t)(k0 + j) * HH + n0 + tx];
    __syncthreads();
    for (int j = ty; j < 32; j += 8) {
        float v = s[tx][j];                      // W[k0+tx][n0+j]
        __nv_bfloat16 h = __float2bfloat16_rn(v);
        __nv_bfloat16 l = __float2bfloat16_rn(v - __bfloat162float(h));
        size_t o = (size_t)(n0 + j) * DD + k0 + tx;
        oh[o] = h;
        ol[o] = l;
    }
}

// =================================================================
// mma.sync GEMM: CTA tile 128x128, BK=64, 8 warps, cp.async 2-stage,
// 3-product bf16 split.  grid = (4, 16, 2), 256 threads.
// =================================================================
#define SKW_B 144                        // smem row stride bytes
#define BUF_BYTES (128 * SKW_B)          // 18432
#define STAGE_BYTES (4 * BUF_BYTES)      // 73728
#define GEMM_SMEM (2 * STAGE_BYTES)      // 147456

__global__ void __launch_bounds__(256, 1)
gemm_mma_kernel(const float* __restrict__ bias_s, const float* __restrict__ bias_e)
{
    extern __shared__ char smem[];
    const int tid = threadIdx.x, wid = tid >> 5, lane = tid & 31;
    const int which = blockIdx.z;
    const int m0 = blockIdx.y * 128, n0 = blockIdx.x * 128;

    const char* gsrc0[4];
    gsrc0[0] = (const char*)(d_Xh + (size_t)m0 * DD);
    gsrc0[1] = (const char*)(d_Xl + (size_t)m0 * DD);
    gsrc0[2] = (const char*)(d_Wth[which] + (size_t)n0 * DD);
    gsrc0[3] = (const char*)(d_Wtl[which] + (size_t)n0 * DD);

    const int lr = tid >> 3;             // 0..31 (row base; +32 per it)
    const int lc = tid & 7;              // 16B column 0..7

    const int warp_m = wid & 3, warp_n = wid >> 2;
    const int aRowOff = (warp_m * 32 + (lane & 15)) * SKW_B;
    const int aColOff = (lane >> 4) * 16;
    const int bRowOff = (warp_n * 64 + (lane & 7) + ((lane >> 4) << 3)) * SKW_B;
    const int bColOff = ((lane >> 3) & 1) * 16;

    float acc[2][8][4];
#pragma unroll
    for (int mt = 0; mt < 2; mt++)
#pragma unroll
        for (int nt = 0; nt < 8; nt++)
#pragma unroll
            for (int q = 0; q < 4; q++) acc[mt][nt][q] = 0.f;

    const uint32_t sstage[2] = { smem_u32(smem), smem_u32(smem + STAGE_BYTES) };

    #define ISSUE_STAGE(c, stg) do {                                          \
        const int kcB = (c) * 128;                                            \
        _Pragma("unroll")                                                     \
        for (int t = 0; t < 4; t++) {                                         \
            uint32_t sbase = sstage[stg] + t * BUF_BYTES;                     \
            const char* g = gsrc0[t] + kcB;                                   \
            _Pragma("unroll")                                                 \
            for (int it = 0; it < 4; it++) {                                  \
                int r = lr + it * 32;                                         \
                uint32_t sa = sbase + r * SKW_B + lc * 16;                    \
                const char* ga = g + (size_t)r * (DD * 2) + lc * 16;          \
                CP_ASYNC16(sa, ga);                                           \
            }                                                                 \
        }                                                                     \
        CP_COMMIT();                                                          \
    } while (0)

    ISSUE_STAGE(0, 0);

    const int pa[3] = {0, 0, 1};
    const int pb[3] = {2, 3, 2};

    for (int c = 0; c < 16; c++) {
        const int stg = c & 1;
        if (c + 1 < 16) { ISSUE_STAGE(c + 1, stg ^ 1); CP_WAIT1(); }
        else            { CP_WAIT0(); }
        __syncthreads();

        const uint32_t sb = sstage[stg];
#pragma unroll
        for (int kk = 0; kk < 4; kk++) {
#pragma unroll
            for (int p = 0; p < 3; p++) {
                const uint32_t ab = sb + pa[p] * BUF_BYTES + aRowOff + kk * 32 + aColOff;
                uint32_t a0[4], a1[4];
                LDSM_X4(a0[0], a0[1], a0[2], a0[3], ab);
                LDSM_X4(a1[0], a1[1], a1[2], a1[3], ab + 16 * SKW_B);

                const uint32_t bbase = sb + pb[p] * BUF_BYTES + bRowOff + kk * 32 + bColOff;
                uint32_t b[4][4];
#pragma unroll
                for (int ntp = 0; ntp < 4; ntp++)
                    LDSM_X4(b[ntp][0], b[ntp][1], b[ntp][2], b[ntp][3],
                            bbase + ntp * 16 * SKW_B);

#pragma unroll
                for (int nt = 0; nt < 8; nt++) {
                    const uint32_t bb0 = b[nt >> 1][(nt & 1) * 2];
                    const uint32_t bb1 = b[nt >> 1][(nt & 1) * 2 + 1];
                    MMA16816(acc[0][nt], a0[0], a0[1], a0[2], a0[3], bb0, bb1);
                    MMA16816(acc[1][nt], a1[0], a1[1], a1[2], a1[3], bb0, bb1);
                }
            }
        }
        __syncthreads();
    }

    const float* bias = which ? bias_e : bias_s;
    float* C = which ? d_he : d_hs;
    const int row0 = m0 + warp_m * 32 + (lane >> 2);
    const int col0 = n0 + warp_n * 64 + (lane & 3) * 2;
#pragma unroll
    for (int mt = 0; mt < 2; mt++) {
#pragma unroll
        for (int nt = 0; nt < 8; nt++) {
            const int row = row0 + mt * 16;
            const int col = col0 + nt * 8;
            const float b0 = bias[col], b1 = bias[col + 1];
            float2 v0 = { acc[mt][nt][0] + b0, acc[mt][nt][1] + b1 };
            float2 v1 = { acc[mt][nt][2] + b0, acc[mt][nt][3] + b1 };
            *(float2*)&C[(size_t)row * HH + col] = v0;
            *(float2*)&C[(size_t)(row + 8) * HH + col] = v1;
        }
    }
}

// =================================================================
// Fused span scoring + key emission + 11-bit histogram pass 0.
// grid = (36 tiles, 8 batches), 256 threads, 2x2/thread.
// =================================================================
__device__ __forceinline__ unsigned fkey(float f)
{
    unsigned u = __float_as_uint(f);
    return (u & 0x80000000u) ? ~u : (u | 0x80000000u);
}
__device__ __forceinline__ float fkey_inv(unsigned k)
{
    unsigned u = (k & 0x80000000u) ? (k & 0x7FFFFFFFu) : ~k;
    return __uint_as_float(u);
}

__device__ __forceinline__ float rdot4(float4 h, float4 e, float4 w)
{
    return fmaxf(h.x + e.x, 0.f) * w.x + fmaxf(h.y + e.y, 0.f) * w.y
         + fmaxf(h.z + e.z, 0.f) * w.z + fmaxf(h.w + e.w, 0.f) * w.w;
}

__device__ __forceinline__ void tile_decode32(int bx, int& ti, int& tj)
{
    int rem = bx;
    for (int r = 0; r < 8; r++) {
        int cnt = 8 - r;
        if (rem < cnt) { ti = r; tj = r + rem; return; }
        rem -= cnt;
    }
    ti = 0; tj = 0;
}

__global__ void __launch_bounds__(256)
score_kernel(const int* __restrict__ input_mask,
             const float* __restrict__ w_score,
             const float* __restrict__ b_score)
{
    const int b = blockIdx.y;
    int ti, tj;
    tile_decode32(blockIdx.x, ti, tj);

    __shared__ float hsS[32][132];
    __shared__ float heS[32][132];
    __shared__ float wS[128];
    __shared__ unsigned hloc[2048];

    const int i0 = ti * 32, j0 = tj * 32;
    const int tid = threadIdx.x;
    const int x = tid & 15, y = tid >> 4;

#pragma unroll
    for (int q = 0; q < 8; q++) hloc[tid + q * 256] = 0u;

    const float* hsBase = d_hs + ((size_t)b * TT + i0) * HH;
    const float* heBase = d_he + ((size_t)b * TT + j0) * HH;

    float acc00 = 0.f, acc01 = 0.f, acc10 = 0.f, acc11 = 0.f;

    for (int ch = 0; ch < HH; ch += 128) {
        __syncthreads();
        if (tid < 32)
            *(float4*)&wS[tid * 4] = *(const float4*)&w_score[ch + tid * 4];
#pragma unroll
        for (int q = 0; q < 4; q++) {
            int idx = tid + q * 256;
            int r = idx >> 5;
            int c4 = (idx & 31) * 4;
            *(float4*)&hsS[r][c4] = *(const float4*)&hsBase[(size_t)r * HH + ch + c4];
            *(float4*)&heS[r][c4] = *(const float4*)&heBase[(size_t)r * HH + ch + c4];
        }
        __syncthreads();

#pragma unroll 4
        for (int c = 0; c < 128; c += 4) {
            float4 w4 = *(float4*)&wS[c];
            float4 hA = *(float4*)&hsS[y][c];
            float4 hB = *(float4*)&hsS[y + 16][c];
            float4 eA = *(float4*)&heS[x][c];
            float4 eB = *(float4*)&heS[x + 16][c];
            acc00 += rdot4(hA, eA, w4);
            acc01 += rdot4(hA, eB, w4);
            acc10 += rdot4(hB, eA, w4);
            acc11 += rdot4(hB, eB, w4);
        }
    }

    const float bsc = *b_score;
    const int iA = i0 + y, iB = i0 + y + 16;
    const int jA = j0 + x, jB = j0 + x + 16;

    const int* mb = input_mask + b * TT;
    unsigned* kb = d_keys + (size_t)b * SS;

    #define EMITK(ii, jj, av)                                                 \
        if ((jj) >= (ii)) {                                                   \
            int s = (2 * (ii) * TT - (ii) * (ii) + (ii)) / 2 + ((jj) - (ii)); \
            bool ok = mb[(ii)] && mb[(jj)];                                   \
            float sv = ok ? ((av) + bsc) : NEGF;                              \
            unsigned k = fkey(sv);                                            \
            kb[s] = k;                                                        \
            atomicAdd(&hloc[k >> 21], 1u);                                    \
        }
    EMITK(iA, jA, acc00)
    EMITK(iA, jB, acc01)
    EMITK(iB, jA, acc10)
    EMITK(iB, jB, acc11)
    #undef EMITK

    __syncthreads();
#pragma unroll
    for (int q = 0; q < 8; q++) {
        int i = tid + q * 256;
        if (hloc[i]) atomicAdd(&d_hist0[b][i], hloc[i]);
    }
}

// =================================================================
// Tail: 11/11/10-digit radix select with 2 barriers + select +
// ticket finalize.  256 blocks x 256 threads.
// =================================================================
// fold a histogram of nb bins (nb = 2048 or 1024).  Each thread owns
// nb/256 consecutive bins in registers; one 256-ladder for totals.
__device__ void fold_n(const unsigned* g, int nb, int shift,
                       unsigned& prefix, unsigned& R,
                       unsigned* sh, unsigned* shv)
{
    const int t = threadIdx.x;
    const int C = nb >> 8;               // 8 or 4
    unsigned v[8];
    unsigned tot = 0;
    for (int c = 0; c < C; c++) { v[c] = g[t * C + c]; tot += v[c]; }
    sh[t] = tot;
    __syncthreads();
    for (int off = 1; off < 256; off <<= 1) {
        unsigned add = (t + off < 256) ? sh[t + off] : 0u;
        __syncthreads();
        sh[t] += add;
        __syncthreads();
    }
    unsigned run = (t < 255) ? sh[t + 1] : 0u;   // suffix above my chunk
    for (int c = C - 1; c >= 0; c--) {
        unsigned sn = run;
        run += v[c];
        if (run >= R && sn < R) { shv[0] = (unsigned)(t * C + c); shv[1] = R - sn; }
    }
    __syncthreads();
    prefix |= shv[0] << (unsigned)shift;
    R = shv[1];
    __syncthreads();
}

__global__ void __launch_bounds__(256)
tail_kernel(const int* __restrict__ answer_spans, float* __restrict__ out)
{
    const int blk = blockIdx.x;          // 0..255
    const int b = blk >> 5, slice = blk & 31;
    const int t = threadIdx.x;
    const int w = t >> 5, lane = t & 31;
    const int s0 = slice * SLICE;
    const unsigned* kb = d_keys + (size_t)b * SS;

    __shared__ unsigned sh[256];
    __shared__ unsigned shv[2];
    __shared__ unsigned hloc[2048];
    __shared__ float redf[256];
    __shared__ int wcnt[8], ecnt[8];
    __shared__ int gold[NUM_GOLD];
    __shared__ int scgHi;
    __shared__ int sh_last;

    // ---- fold 0 (11 bits from score) ----
    unsigned prefix = 0u, R = K_TOP;
    fold_n(d_hist0[b], 2048, 21, prefix, R, sh, shv);
    const unsigned p11 = prefix >> 21;

    // ---- scan 1: filter top-11, histogram next 11 bits ----
#pragma unroll
    for (int q = 0; q < 8; q++) hloc[t + q * 256] = 0u;
    __syncthreads();
    for (int q = t; q < SLICE; q += 256) {
        unsigned u = kb[s0 + q];
        if ((u >> 21) == p11)
            atomicAdd(&hloc[(u >> 10) & 0x7FFu], 1u);
    }
    __syncthreads();
#pragma unroll
    for (int q = 0; q < 8; q++) {
        int i = t + q * 256;
        if (hloc[i]) atomicAdd(&d_hist1[b][i], hloc[i]);
    }
    batch_barrier(b, 32u);

    // ---- fold 1, then scan 2: last 10 bits + cgHi + suffix pub ----
    fold_n(d_hist1[b], 2048, 10, prefix, R, sh, shv);
    const unsigned p22 = prefix >> 10;

#pragma unroll
    for (int q = 0; q < 4; q++) hloc[t + q * 256] = 0u;
    if (t == 0) scgHi = 0;
    __syncthreads();
    {
        int cgHi = 0;
        for (int q = t; q < SLICE; q += 256) {
            unsigned u = kb[s0 + q];
            unsigned hi = u >> 10;
            if (hi == p22) atomicAdd(&hloc[u & 0x3FFu], 1u);
            else if (hi > p22) cgHi++;
        }
        if (cgHi) atomicAdd(&scgHi, cgHi);
    }
    __syncthreads();
    // publish local suffix sums of the 1024-bin hloc, then merge global
    {
        unsigned v[4];
        unsigned tot = 0;
#pragma unroll
        for (int c = 0; c < 4; c++) { v[c] = hloc[t * 4 + c]; tot += v[c]; }
        sh[t] = tot;
        __syncthreads();
        for (int off = 1; off < 256; off <<= 1) {
            unsigned add = (t + off < 256) ? sh[t + off] : 0u;
            __syncthreads();
            sh[t] += add;
            __syncthreads();
        }
        unsigned run = (t < 255) ? sh[t + 1] : 0u;
#pragma unroll
        for (int c = 3; c >= 0; c--) {
            run += v[c];
            d_suff[blk][t * 4 + c] = (int)run;
        }
        if (t == 0) { d_suff[blk][1024] = 0; d_cgHi[blk] = scgHi; }
#pragma unroll
        for (int c = 0; c < 4; c++)
            if (v[c]) atomicAdd(&d_hist2[b][t * 4 + c], v[c]);
    }
    batch_barrier(b, 64u);

    // ---- fold 2 -> exact threshold ----
    fold_n(d_hist2[b], 1024, 0, prefix, R, sh, shv);
    const unsigned thresh = prefix;
    const int numEq = (int)R;
    const int dstar = (int)(thresh & 0x3FFu);

    // ---- select: ordered positioned writes ----
    {
        int rg = 0, re = 0;
        for (int sl = 0; sl < slice; sl++) {
            int bb = (b << 5) + sl;
            int sA = d_suff[bb][dstar];
            int sB = d_suff[bb][dstar + 1];
            rg += d_cgHi[bb] + sB;
            re += sA - sB;
        }
        const unsigned lt = (1u << lane) - 1u;
        for (int c0 = 0; c0 < SLICE; c0 += 256) {
            int q = c0 + t;
            bool valid = q < SLICE;
            unsigned u = valid ? kb[s0 + q] : 0u;
            bool g = valid && (u > thresh);
            bool e = valid && (u == thresh);
            unsigned bg = __ballot_sync(0xffffffffu, g);
            unsigned be = __ballot_sync(0xffffffffu, e);
            if (lane == 0) { wcnt[w] = __popc(bg); ecnt[w] = __popc(be); }
            __syncthreads();
            int exg = 0, exe = 0, tg = 0, te = 0;
#pragma unroll
            for (int ww = 0; ww < 8; ww++) {
                if (ww < w) { exg += wcnt[ww]; exe += ecnt[ww]; }
                tg += wcnt[ww]; te += ecnt[ww];
            }
            if (g || e) {
                int mg = __popc(bg & lt), me = __popc(be & lt);
                int gBefore = rg + exg + mg;
                int eBefore = re + exe + me;
                bool sel = g || (eBefore < numEq);
                int pos = gBefore + min(eBefore, numEq);
                if (sel && pos < K_TOP) {
                    d_topidx[b * K_TOP + pos] = s0 + q;
                    d_toplog[b * K_TOP + pos] = fkey_inv(u);
                }
            }
            __syncthreads();
            rg += tg; re += te;
        }
    }

    // ---- per-batch finalize ticket: last block of batch finalizes ----
    __syncthreads();
    if (t == 0) {
        __threadfence();
        unsigned v = atomicAdd(&d_batchdone[b], 1u);
        sh_last = (v == 31u) ? 1 : 0;
    }
    __syncthreads();

    if (sh_last) {
        __threadfence();
        if (t < NUM_GOLD) {
            int g0 = answer_spans[(b * NUM_GOLD + t) * 2 + 0];
            int e0 = answer_spans[(b * NUM_GOLD + t) * 2 + 1];
            int idx = (2 * g0 * TT - g0 * g0 + g0) / 2 + (e0 - g0);
            gold[t] = (g0 >= 0) ? idx : -1;
        }
        __syncthreads();
        float lsum = 0.f;
#pragma unroll
        for (int r2 = 0; r2 < 2; r2++) {
            int k = t + r2 * 256;
            int sIdx = d_topidx[b * K_TOP + k];
            float l = d_toplog[b * K_TOP + k];
            float m = (l > -1e19f) ? 1.f : 0.f;
            float pred = 0.f;
#pragma unroll
            for (int g2 = 0; g2 < NUM_GOLD; g2++)
                if (gold[g2] == sIdx) pred = 1.f;
            out[b * K_TOP + k] = (1.f / (1.f + expf(-l))) * m;
            lsum += m * (fmaxf(l, 0.f) - l * pred + log1pf(expf(-fabsf(l))));
        }
        redf[t] = lsum;
        __syncthreads();
        for (int st = 128; st > 0; st >>= 1) {
            if (t < st) redf[t] += redf[t + st];
            __syncthreads();
        }
        if (t == 0) {
            d_losspart[b] = redf[0];
            d_batchdone[b] = 0u;          // reset for next replay
            d_barctr[b] = 0u;             // reset per-batch barrier
            __threadfence();
            unsigned v = atomicAdd(&d_done, 1u);
            if (v == BB - 1) {
                float ssum = 0.f;
                for (int q2 = 0; q2 < BB; q2++) ssum += d_losspart[q2];
                out[BB * K_TOP] = ssum;
                d_done = 0u;
            }
        }
    }
}

// =================================================================
// Launch — 4 graph nodes
// =================================================================
extern "C" void kernel_launch(void* const* d_in, const int* in_sizes, int n_in,
                              void* d_out, int out_size)
{
    const float* inputs       = (const float*)d_in[0];
    const int*   input_mask   = (const int*)d_in[1];
    const int*   answer_spans = (const int*)d_in[2];
    const float* W_start      = (const float*)d_in[3];
    const float* b_start      = (const float*)d_in[4];
    const float* W_end        = (const float*)d_in[5];
    const float* b_end        = (const float*)d_in[6];
    const float* w_score      = (const float*)d_in[7];
    const float* b_score      = (const float*)d_in[8];
    float* out = (float*)d_out;

    static int smem_set = 0;
    if (!smem_set) {
        cudaFuncSetAttribute(gemm_mma_kernel,
                             cudaFuncAttributeMaxDynamicSharedMemorySize, GEMM_SMEM);
        smem_set = 1;
    }

    fused_convert_kernel<<<3072, 256>>>(inputs, W_start, W_end);

    dim3 gGemm(HH / 128, M_TOT / 128, 2);   // (4, 16, 2)
    gemm_mma_kernel<<<gGemm, 256, GEMM_SMEM>>>(b_start, b_end);

    dim3 gScore(36, BB);
    score_kernel<<<gScore, 256>>>(input_mask, w_score, b_score);

    tail_kernel<<<FRB, 256>>>(answer_spans, out);
}

// round 16
// speedup vs baseline: 1.0013x; 1.0013x over previous
#include <cuda_runtime.h>
#include <cuda_bf16.h>
#include <cstdint>
#include <math.h>

#define BB 8
#define TT 256
#define DD 1024
#define HH 512
#define SS 32896      // T*(T+1)/2 = 32*1028
#define K_TOP 512
#define NUM_GOLD 10
#define NEGF (-1e20f)

#define M_TOT (BB * TT)   // 2048
#define SLICE 1028        // SS / 32
#define FRB 256           // tail block count (32 per batch)

// ---------------- scratch (no allocation allowed) ----------------
__device__ float d_hs[M_TOT * HH];              // 4 MB
__device__ float d_he[M_TOT * HH];              // 4 MB
__device__ unsigned d_keys[BB * SS];            // ~1 MB radix keys
__device__ int   d_topidx[BB * K_TOP];
__device__ float d_toplog[BB * K_TOP];
__device__ float d_losspart[BB];

__device__ unsigned d_hist0[BB][2048];          // 11-bit pass (from score)
__device__ unsigned d_hist1[BB][2048];          // 11-bit pass
__device__ unsigned d_hist2[BB][1024];          // 10-bit pass
__device__ int d_suff[FRB][1025];
__device__ int d_cgHi[FRB];
__device__ unsigned d_batchdone[BB];
__device__ unsigned d_done;
__device__ unsigned d_barctr[BB];

__device__ __nv_bfloat16 d_Xh[M_TOT * DD];      // 4 MB
__device__ __nv_bfloat16 d_Xl[M_TOT * DD];      // 4 MB
__device__ __nv_bfloat16 d_Wth[2][HH * DD];     // W^T hi, [n,k]
__device__ __nv_bfloat16 d_Wtl[2][HH * DD];     // W^T lo, [n,k]

// ======================= helpers ============================
__device__ __forceinline__ uint32_t smem_u32(const void* p)
{
    uint32_t a;
    asm("{ .reg .u64 t; cvta.to.shared.u64 t, %1; cvt.u32.u64 %0, t; }"
        : "=r"(a) : "l"(p));
    return a;
}

#define LDSM_X4(r0, r1, r2, r3, addr) \
    asm volatile("ldmatrix.sync.aligned.m8n8.x4.shared.b16 {%0,%1,%2,%3}, [%4];" \
                 : "=r"(r0), "=r"(r1), "=r"(r2), "=r"(r3) : "r"(addr))

#define MMA16816(d, a0, a1, a2, a3, b0, b1) \
    asm volatile("mma.sync.aligned.m16n8k16.row.col.f32.bf16.bf16.f32 " \
                 "{%0,%1,%2,%3}, {%4,%5,%6,%7}, {%8,%9}, {%0,%1,%2,%3};" \
                 : "+f"((d)[0]), "+f"((d)[1]), "+f"((d)[2]), "+f"((d)[3]) \
                 : "r"(a0), "r"(a1), "r"(a2), "r"(a3), "r"(b0), "r"(b1))

#define CP_ASYNC16(saddr, gaddr) \
    asm volatile("cp.async.cg.shared.global [%0], [%1], 16;" \
                 :: "r"(saddr), "l"(gaddr))
#define CP_COMMIT()  asm volatile("cp.async.commit_group;" ::: "memory")
#define CP_WAIT1()   asm volatile("cp.async.wait_group 1;" ::: "memory")
#define CP_WAIT0()   asm volatile("cp.async.wait_group 0;" ::: "memory")

// per-batch software grid barrier — BOUNDED spin (latent bug => garbage,
// not a dead container).  32 blocks per batch, all co-resident.
__device__ __forceinline__ void batch_barrier(int b, unsigned target)
{
    __syncthreads();
    if (threadIdx.x == 0) {
        __threadfence();
        atomicAdd(&d_barctr[b], 1u);
        for (int it = 0; it < 10000000; it++) {
            if (*(volatile unsigned*)&d_barctr[b] >= target) break;
        }
        __threadfence();
    }
    __syncthreads();
}

// =================================================================
// Fused conversion: X split (blocks 0..2047) + W transpose/split
// + cross-launch state zeroing.
// =================================================================
__global__ void __launch_bounds__(256)
fused_convert_kernel(const float* __restrict__ X,
                     const float* __restrict__ Ws, const float* __restrict__ We)
{
    const int tid = threadIdx.x;
    if (blockIdx.x < 2048) {
        int i = blockIdx.x * 256 + tid;          // float4 index
        float4 v = ((const float4*)X)[i];
        __nv_bfloat16 h0 = __float2bfloat16_rn(v.x);
        __nv_bfloat16 h1 = __float2bfloat16_rn(v.y);
        __nv_bfloat16 h2 = __float2bfloat16_rn(v.z);
        __nv_bfloat16 h3 = __float2bfloat16_rn(v.w);
        __nv_bfloat16 l0 = __float2bfloat16_rn(v.x - __bfloat162float(h0));
        __nv_bfloat16 l1 = __float2bfloat16_rn(v.y - __bfloat162float(h1));
        __nv_bfloat16 l2 = __float2bfloat16_rn(v.z - __bfloat162float(h2));
        __nv_bfloat16 l3 = __float2bfloat16_rn(v.w - __bfloat162float(h3));
        ((__nv_bfloat162*)d_Xh)[2 * i]     = __nv_bfloat162(h0, h1);
        ((__nv_bfloat162*)d_Xh)[2 * i + 1] = __nv_bfloat162(h2, h3);
        ((__nv_bfloat162*)d_Xl)[2 * i]     = __nv_bfloat162(l0, l1);
        ((__nv_bfloat162*)d_Xl)[2 * i + 1] = __nv_bfloat162(l2, l3);
        return;
    }

    const int wb = blockIdx.x - 2048;            // 0..1023
    if (wb == 0) {
        unsigned* h0p = (unsigned*)d_hist0;
        unsigned* h1p = (unsigned*)d_hist1;
        unsigned* h2p = (unsigned*)d_hist2;
        for (int i = tid; i < BB * 2048; i += 256) { h0p[i] = 0u; h1p[i] = 0u; }
        for (int i = tid; i < BB * 1024; i += 256) h2p[i] = 0u;
        if (tid < BB) { d_batchdone[tid] = 0u; d_barctr[tid] = 0u; }
        if (tid == 0) d_done = 0u;
    }
    const int z = wb >> 9;                       // 0/1
    const int rem = wb & 511;
    const int n0 = (rem & 15) * 32;              // 16 n-tiles
    const int k0 = (rem >> 4) * 32;              // 32 k-tiles

    const float* W = z ? We : Ws;
    __nv_bfloat16* oh = d_Wth[z];
    __nv_bfloat16* ol = d_Wtl[z];

    __shared__ float s[32][33];
    const int tx = tid & 31, ty = tid >> 5;      // 32x8

    for (int j = ty; j < 32; j += 8)
        s[j][tx] = W[(size_t)(k0 + j) * HH + n0 + tx];
    __syncthreads();
    for (int j = ty; j < 32; j += 8) {
        float v = s[tx][j];                      // W[k0+tx][n0+j]
        __nv_bfloat16 h = __float2bfloat16_rn(v);
        __nv_bfloat16 l = __float2bfloat16_rn(v - __bfloat162float(h));
        size_t o = (size_t)(n0 + j) * DD + k0 + tx;
        oh[o] = h;
        ol[o] = l;
    }
}

// =================================================================
// mma.sync GEMM: CTA tile 128x128, BK=64, 8 warps, cp.async 2-stage,
// 3-product bf16 split.  grid = (4, 16, 2), 256 threads.
// =================================================================
#define SKW_B 144                        // smem row stride bytes
#define BUF_BYTES (128 * SKW_B)          // 18432
#define STAGE_BYTES (4 * BUF_BYTES)      // 73728
#define GEMM_SMEM (2 * STAGE_BYTES)      // 147456

__global__ void __launch_bounds__(256, 1)
gemm_mma_kernel(const float* __restrict__ bias_s, const float* __restrict__ bias_e)
{
    extern __shared__ char smem[];
    const int tid = threadIdx.x, wid = tid >> 5, lane = tid & 31;
    const int which = blockIdx.z;
    const int m0 = blockIdx.y * 128, n0 = blockIdx.x * 128;

    const char* gsrc0[4];
    gsrc0[0] = (const char*)(d_Xh + (size_t)m0 * DD);
    gsrc0[1] = (const char*)(d_Xl + (size_t)m0 * DD);
    gsrc0[2] = (const char*)(d_Wth[which] + (size_t)n0 * DD);
    gsrc0[3] = (const char*)(d_Wtl[which] + (size_t)n0 * DD);

    const int lr = tid >> 3;             // 0..31 (row base; +32 per it)
    const int lc = tid & 7;              // 16B column 0..7

    const int warp_m = wid & 3, warp_n = wid >> 2;
    const int aRowOff = (warp_m * 32 + (lane & 15)) * SKW_B;
    const int aColOff = (lane >> 4) * 16;
    const int bRowOff = (warp_n * 64 + (lane & 7) + ((lane >> 4) << 3)) * SKW_B;
    const int bColOff = ((lane >> 3) & 1) * 16;

    float acc[2][8][4];
#pragma unroll
    for (int mt = 0; mt < 2; mt++)
#pragma unroll
        for (int nt = 0; nt < 8; nt++)
#pragma unroll
            for (int q = 0; q < 4; q++) acc[mt][nt][q] = 0.f;

    const uint32_t sstage[2] = { smem_u32(smem), smem_u32(smem + STAGE_BYTES) };

    #define ISSUE_STAGE(c, stg) do {                                          \
        const int kcB = (c) * 128;                                            \
        _Pragma("unroll")                                                     \
        for (int t = 0; t < 4; t++) {                                         \
            uint32_t sbase = sstage[stg] + t * BUF_BYTES;                     \
            const char* g = gsrc0[t] + kcB;                                   \
            _Pragma("unroll")                                                 \
            for (int it = 0; it < 4; it++) {                                  \
                int r = lr + it * 32;                                         \
                uint32_t sa = sbase + r * SKW_B + lc * 16;                    \
                const char* ga = g + (size_t)r * (DD * 2) + lc * 16;          \
                CP_ASYNC16(sa, ga);                                           \
            }                                                                 \
        }                                                                     \
        CP_COMMIT();                                                          \
    } while (0)

    ISSUE_STAGE(0, 0);

    const int pa[3] = {0, 0, 1};
    const int pb[3] = {2, 3, 2};

    for (int c = 0; c < 16; c++) {
        const int stg = c & 1;
        if (c + 1 < 16) { ISSUE_STAGE(c + 1, stg ^ 1); CP_WAIT1(); }
        else            { CP_WAIT0(); }
        __syncthreads();

        const uint32_t sb = sstage[stg];
#pragma unroll
        for (int kk = 0; kk < 4; kk++) {
#pragma unroll
            for (int p = 0; p < 3; p++) {
                const uint32_t ab = sb + pa[p] * BUF_BYTES + aRowOff + kk * 32 + aColOff;
                uint32_t a0[4], a1[4];
                LDSM_X4(a0[0], a0[1], a0[2], a0[3], ab);
                LDSM_X4(a1[0], a1[1], a1[2], a1[3], ab + 16 * SKW_B);

                const uint32_t bbase = sb + pb[p] * BUF_BYTES + bRowOff + kk * 32 + bColOff;
                uint32_t b[4][4];
#pragma unroll
                for (int ntp = 0; ntp < 4; ntp++)
                    LDSM_X4(b[ntp][0], b[ntp][1], b[ntp][2], b[ntp][3],
                            bbase + ntp * 16 * SKW_B);

#pragma unroll
                for (int nt = 0; nt < 8; nt++) {
                    const uint32_t bb0 = b[nt >> 1][(nt & 1) * 2];
                    const uint32_t bb1 = b[nt >> 1][(nt & 1) * 2 + 1];
                    MMA16816(acc[0][nt], a0[0], a0[1], a0[2], a0[3], bb0, bb1);
                    MMA16816(acc[1][nt], a1[0], a1[1], a1[2], a1[3], bb0, bb1);
                }
            }
        }
        __syncthreads();
    }

    const float* bias = which ? bias_e : bias_s;
    float* C = which ? d_he : d_hs;
    const int row0 = m0 + warp_m * 32 + (lane >> 2);
    const int col0 = n0 + warp_n * 64 + (lane & 3) * 2;
#pragma unroll
    for (int mt = 0; mt < 2; mt++) {
#pragma unroll
        for (int nt = 0; nt < 8; nt++) {
            const int row = row0 + mt * 16;
            const int col = col0 + nt * 8;
            const float b0 = bias[col], b1 = bias[col + 1];
            float2 v0 = { acc[mt][nt][0] + b0, acc[mt][nt][1] + b1 };
            float2 v1 = { acc[mt][nt][2] + b0, acc[mt][nt][3] + b1 };
            *(float2*)&C[(size_t)row * HH + col] = v0;
            *(float2*)&C[(size_t)(row + 8) * HH + col] = v1;
        }
    }
}

// =================================================================
// Fused span scoring + key emission + 11-bit histogram pass 0.
// grid = (36 tiles, 8 batches), 256 threads, 2x2/thread.
// Component-parallel accumulators: 16 independent FMA chains/thread.
// =================================================================
__device__ __forceinline__ unsigned fkey(float f)
{
    unsigned u = __float_as_uint(f);
    return (u & 0x80000000u) ? ~u : (u | 0x80000000u);
}
__device__ __forceinline__ float fkey_inv(unsigned k)
{
    unsigned u = (k & 0x80000000u) ? (k & 0x7FFFFFFFu) : ~k;
    return __uint_as_float(u);
}

__device__ __forceinline__ void racc(float4& acc, float4 h, float4 e, float4 w)
{
    acc.x = fmaf(fmaxf(h.x + e.x, 0.f), w.x, acc.x);
    acc.y = fmaf(fmaxf(h.y + e.y, 0.f), w.y, acc.y);
    acc.z = fmaf(fmaxf(h.z + e.z, 0.f), w.z, acc.z);
    acc.w = fmaf(fmaxf(h.w + e.w, 0.f), w.w, acc.w);
}

__device__ __forceinline__ float hsum4(float4 a)
{
    return (a.x + a.y) + (a.z + a.w);
}

__device__ __forceinline__ void tile_decode32(int bx, int& ti, int& tj)
{
    int rem = bx;
    for (int r = 0; r < 8; r++) {
        int cnt = 8 - r;
        if (rem < cnt) { ti = r; tj = r + rem; return; }
        rem -= cnt;
    }
    ti = 0; tj = 0;
}

__global__ void __launch_bounds__(256)
score_kernel(const int* __restrict__ input_mask,
             const float* __restrict__ w_score,
             const float* __restrict__ b_score)
{
    const int b = blockIdx.y;
    int ti, tj;
    tile_decode32(blockIdx.x, ti, tj);

    __shared__ float hsS[32][132];
    __shared__ float heS[32][132];
    __shared__ float wS[128];
    __shared__ unsigned hloc[2048];

    const int i0 = ti * 32, j0 = tj * 32;
    const int tid = threadIdx.x;
    const int x = tid & 15, y = tid >> 4;

#pragma unroll
    for (int q = 0; q < 8; q++) hloc[tid + q * 256] = 0u;

    const float* hsBase = d_hs + ((size_t)b * TT + i0) * HH;
    const float* heBase = d_he + ((size_t)b * TT + j0) * HH;

    float4 a00 = {0.f, 0.f, 0.f, 0.f}, a01 = {0.f, 0.f, 0.f, 0.f};
    float4 a10 = {0.f, 0.f, 0.f, 0.f}, a11 = {0.f, 0.f, 0.f, 0.f};

    for (int ch = 0; ch < HH; ch += 128) {
        __syncthreads();
        if (tid < 32)
            *(float4*)&wS[tid * 4] = *(const float4*)&w_score[ch + tid * 4];
#pragma unroll
        for (int q = 0; q < 4; q++) {
            int idx = tid + q * 256;
            int r = idx >> 5;
            int c4 = (idx & 31) * 4;
            *(float4*)&hsS[r][c4] = *(const float4*)&hsBase[(size_t)r * HH + ch + c4];
            *(float4*)&heS[r][c4] = *(const float4*)&heBase[(size_t)r * HH + ch + c4];
        }
        __syncthreads();

#pragma unroll 4
        for (int c = 0; c < 128; c += 4) {
            float4 w4 = *(float4*)&wS[c];
            float4 hA = *(float4*)&hsS[y][c];
            float4 hB = *(float4*)&hsS[y + 16][c];
            float4 eA = *(float4*)&heS[x][c];
            float4 eB = *(float4*)&heS[x + 16][c];
            racc(a00, hA, eA, w4);
            racc(a01, hA, eB, w4);
            racc(a10, hB, eA, w4);
            racc(a11, hB, eB, w4);
        }
    }

    const float acc00 = hsum4(a00), acc01 = hsum4(a01);
    const float acc10 = hsum4(a10), acc11 = hsum4(a11);

    const float bsc = *b_score;
    const int iA = i0 + y, iB = i0 + y + 16;
    const int jA = j0 + x, jB = j0 + x + 16;

    const int* mb = input_mask + b * TT;
    unsigned* kb = d_keys + (size_t)b * SS;

    #define EMITK(ii, jj, av)                                                 \
        if ((jj) >= (ii)) {                                                   \
            int s = (2 * (ii) * TT - (ii) * (ii) + (ii)) / 2 + ((jj) - (ii)); \
            bool ok = mb[(ii)] && mb[(jj)];                                   \
            float sv = ok ? ((av) + bsc) : NEGF;                              \
            unsigned k = fkey(sv);                                            \
            kb[s] = k;                                                        \
            atomicAdd(&hloc[k >> 21], 1u);                                    \
        }
    EMITK(iA, jA, acc00)
    EMITK(iA, jB, acc01)
    EMITK(iB, jA, acc10)
    EMITK(iB, jB, acc11)
    #undef EMITK

    __syncthreads();
#pragma unroll
    for (int q = 0; q < 8; q++) {
        int i = tid + q * 256;
        if (hloc[i]) atomicAdd(&d_hist0[b][i], hloc[i]);
    }
}

// =================================================================
// Tail: 11/11/10-digit radix select with 2 barriers + select +
// ticket finalize.  256 blocks x 256 threads.
// =================================================================
__device__ void fold_n(const unsigned* g, int nb, int shift,
                       unsigned& prefix, unsigned& R,
                       unsigned* sh, unsigned* shv)
{
    const int t = threadIdx.x;
    const int C = nb >> 8;               // 8 or 4
    unsigned v[8];
    unsigned tot = 0;
    for (int c = 0; c < C; c++) { v[c] = g[t * C + c]; tot += v[c]; }
    sh[t] = tot;
    __syncthreads();
    for (int off = 1; off < 256; off <<= 1) {
        unsigned add = (t + off < 256) ? sh[t + off] : 0u;
        __syncthreads();
        sh[t] += add;
        __syncthreads();
    }
    unsigned run = (t < 255) ? sh[t + 1] : 0u;   // suffix above my chunk
    for (int c = C - 1; c >= 0; c--) {
        unsigned sn = run;
        run += v[c];
        if (run >= R && sn < R) { shv[0] = (unsigned)(t * C + c); shv[1] = R - sn; }
    }
    __syncthreads();
    prefix |= shv[0] << (unsigned)shift;
    R = shv[1];
    __syncthreads();
}

__global__ void __launch_bounds__(256)
tail_kernel(const int* __restrict__ answer_spans, float* __restrict__ out)
{
    const int blk = blockIdx.x;          // 0..255
    const int b = blk >> 5, slice = blk & 31;
    const int t = threadIdx.x;
    const int w = t >> 5, lane = t & 31;
    const int s0 = slice * SLICE;
    const unsigned* kb = d_keys + (size_t)b * SS;

    __shared__ unsigned sh[256];
    __shared__ unsigned shv[2];
    __shared__ unsigned hloc[2048];
    __shared__ float redf[256];
    __shared__ int wcnt[8], ecnt[8];
    __shared__ int gold[NUM_GOLD];
    __shared__ int scgHi;
    __shared__ int sh_last;

    // ---- fold 0 (11 bits from score) ----
    unsigned prefix = 0u, R = K_TOP;
    fold_n(d_hist0[b], 2048, 21, prefix, R, sh, shv);
    const unsigned p11 = prefix >> 21;

    // ---- scan 1: filter top-11, histogram next 11 bits ----
#pragma unroll
    for (int q = 0; q < 8; q++) hloc[t + q * 256] = 0u;
    __syncthreads();
    for (int q = t; q < SLICE; q += 256) {
        unsigned u = kb[s0 + q];
        if ((u >> 21) == p11)
            atomicAdd(&hloc[(u >> 10) & 0x7FFu], 1u);
    }
    __syncthreads();
#pragma unroll
    for (int q = 0; q < 8; q++) {
        int i = t + q * 256;
        if (hloc[i]) atomicAdd(&d_hist1[b][i], hloc[i]);
    }
    batch_barrier(b, 32u);

    // ---- fold 1, then scan 2: last 10 bits + cgHi + suffix pub ----
    fold_n(d_hist1[b], 2048, 10, prefix, R, sh, shv);
    const unsigned p22 = prefix >> 10;

#pragma unroll
    for (int q = 0; q < 4; q++) hloc[t + q * 256] = 0u;
    if (t == 0) scgHi = 0;
    __syncthreads();
    {
        int cgHi = 0;
        for (int q = t; q < SLICE; q += 256) {
            unsigned u = kb[s0 + q];
            unsigned hi = u >> 10;
            if (hi == p22) atomicAdd(&hloc[u & 0x3FFu], 1u);
            else if (hi > p22) cgHi++;
        }
        if (cgHi) atomicAdd(&scgHi, cgHi);
    }
    __syncthreads();
    // publish local suffix sums of the 1024-bin hloc, then merge global
    {
        unsigned v[4];
        unsigned tot = 0;
#pragma unroll
        for (int c = 0; c < 4; c++) { v[c] = hloc[t * 4 + c]; tot += v[c]; }
        sh[t] = tot;
        __syncthreads();
        for (int off = 1; off < 256; off <<= 1) {
            unsigned add = (t + off < 256) ? sh[t + off] : 0u;
            __syncthreads();
            sh[t] += add;
            __syncthreads();
        }
        unsigned run = (t < 255) ? sh[t + 1] : 0u;
#pragma unroll
        for (int c = 3; c >= 0; c--) {
            run += v[c];
            d_suff[blk][t * 4 + c] = (int)run;
        }
        if (t == 0) { d_suff[blk][1024] = 0; d_cgHi[blk] = scgHi; }
#pragma unroll
        for (int c = 0; c < 4; c++)
            if (v[c]) atomicAdd(&d_hist2[b][t * 4 + c], v[c]);
    }
    batch_barrier(b, 64u);

    // ---- fold 2 -> exact threshold ----
    fold_n(d_hist2[b], 1024, 0, prefix, R, sh, shv);
    const unsigned thresh = prefix;
    const int numEq = (int)R;
    const int dstar = (int)(thresh & 0x3FFu);

    // ---- select: ordered positioned writes ----
    {
        int rg = 0, re = 0;
        for (int sl = 0; sl < slice; sl++) {
            int bb = (b << 5) + sl;
            int sA = d_suff[bb][dstar];
            int sB = d_suff[bb][dstar + 1];
            rg += d_cgHi[bb] + sB;
            re += sA - sB;
        }
        const unsigned lt = (1u << lane) - 1u;
        for (int c0 = 0; c0 < SLICE; c0 += 256) {
            int q = c0 + t;
            bool valid = q < SLICE;
            unsigned u = valid ? kb[s0 + q] : 0u;
            bool g = valid && (u > thresh);
            bool e = valid && (u == thresh);
            unsigned bg = __ballot_sync(0xffffffffu, g);
            unsigned be = __ballot_sync(0xffffffffu, e);
            if (lane == 0) { wcnt[w] = __popc(bg); ecnt[w] = __popc(be); }
            __syncthreads();
            int exg = 0, exe = 0, tg = 0, te = 0;
#pragma unroll
            for (int ww = 0; ww < 8; ww++) {
                if (ww < w) { exg += wcnt[ww]; exe += ecnt[ww]; }
                tg += wcnt[ww]; te += ecnt[ww];
            }
            if (g || e) {
                int mg = __popc(bg & lt), me = __popc(be & lt);
                int gBefore = rg + exg + mg;
                int eBefore = re + exe + me;
                bool sel = g || (eBefore < numEq);
                int pos = gBefore + min(eBefore, numEq);
                if (sel && pos < K_TOP) {
                    d_topidx[b * K_TOP + pos] = s0 + q;
                    d_toplog[b * K_TOP + pos] = fkey_inv(u);
                }
            }
            __syncthreads();
            rg += tg; re += te;
        }
    }

    // ---- per-batch finalize ticket: last block of batch finalizes ----
    __syncthreads();
    if (t == 0) {
        __threadfence();
        unsigned v = atomicAdd(&d_batchdone[b], 1u);
        sh_last = (v == 31u) ? 1 : 0;
    }
    __syncthreads();

    if (sh_last) {
        __threadfence();
        if (t < NUM_GOLD) {
            int g0 = answer_spans[(b * NUM_GOLD + t) * 2 + 0];
            int e0 = answer_spans[(b * NUM_GOLD + t) * 2 + 1];
            int idx = (2 * g0 * TT - g0 * g0 + g0) / 2 + (e0 - g0);
            gold[t] = (g0 >= 0) ? idx : -1;
        }
        __syncthreads();
        float lsum = 0.f;
#pragma unroll
        for (int r2 = 0; r2 < 2; r2++) {
            int k = t + r2 * 256;
            int sIdx = d_topidx[b * K_TOP + k];
            float l = d_toplog[b * K_TOP + k];
            float m = (l > -1e19f) ? 1.f : 0.f;
            float pred = 0.f;
#pragma unroll
            for (int g2 = 0; g2 < NUM_GOLD; g2++)
                if (gold[g2] == sIdx) pred = 1.f;
            out[b * K_TOP + k] = (1.f / (1.f + expf(-l))) * m;
            lsum += m * (fmaxf(l, 0.f) - l * pred + log1pf(expf(-fabsf(l))));
        }
        redf[t] = lsum;
        __syncthreads();
        for (int st = 128; st > 0; st >>= 1) {
            if (t < st) redf[t] += redf[t + st];
            __syncthreads();
        }
        if (t == 0) {
            d_losspart[b] = redf[0];
            d_batchdone[b] = 0u;          // reset for next replay
            d_barctr[b] = 0u;             // reset per-batch barrier
            __threadfence();
            unsigned v = atomicAdd(&d_done, 1u);
            if (v == BB - 1) {
                float ssum = 0.f;
                for (int q2 = 0; q2 < BB; q2++) ssum += d_losspart[q2];
                out[BB * K_TOP] = ssum;
                d_done = 0u;
            }
        }
    }
}

// =================================================================
// Launch — 4 graph nodes
// =================================================================
extern "C" void kernel_launch(void* const* d_in, const int* in_sizes, int n_in,
                              void* d_out, int out_size)
{
    const float* inputs       = (const float*)d_in[0];
    const int*   input_mask   = (const int*)d_in[1];
    const int*   answer_spans = (const int*)d_in[2];
    const float* W_start      = (const float*)d_in[3];
    const float* b_start      = (const float*)d_in[4];
    const float* W_end        = (const float*)d_in[5];
    const float* b_end        = (const float*)d_in[6];
    const float* w_score      = (const float*)d_in[7];
    const float* b_score      = (const float*)d_in[8];
    float* out = (float*)d_out;

    static int smem_set = 0;
    if (!smem_set) {
        cudaFuncSetAttribute(gemm_mma_kernel,
                             cudaFuncAttributeMaxDynamicSharedMemorySize, GEMM_SMEM);
        smem_set = 1;
    }

    fused_convert_kernel<<<3072, 256>>>(inputs, W_start, W_end);

    dim3 gGemm(HH / 128, M_TOT / 128, 2);   // (4, 16, 2)
    gemm_mma_kernel<<<gGemm, 256, GEMM_SMEM>>>(b_start, b_end);

    dim3 gScore(36, BB);
    score_kernel<<<gScore, 256>>>(input_mask, w_score, b_score);

    tail_kernel<<<FRB, 256>>>(answer_spans, out);
}

// round 17
// speedup vs baseline: 1.0198x; 1.0185x over previous
#include <cuda_runtime.h>
#include <cuda_bf16.h>
#include <cstdint>
#include <math.h>

#define BB 8
#define TT 256
#define DD 1024
#define HH 512
#define SS 32896      // T*(T+1)/2 = 32*1028
#define K_TOP 512
#define NUM_GOLD 10
#define NEGF (-1e20f)

#define M_TOT (BB * TT)   // 2048
#define SLICE 1028        // SS / 32
#define FRB 256           // tail block count (32 per batch)

// ---------------- scratch (no allocation allowed) ----------------
__device__ float d_hs[M_TOT * HH];              // 4 MB
__device__ float d_he[M_TOT * HH];              // 4 MB
__device__ unsigned d_keys[BB * SS];            // ~1 MB radix keys
__device__ int   d_topidx[BB * K_TOP];
__device__ float d_toplog[BB * K_TOP];
__device__ float d_losspart[BB];

__device__ unsigned d_hist0[BB][2048];          // 11-bit pass (from score)
__device__ unsigned d_hist1[BB][2048];          // 11-bit pass
__device__ unsigned d_hist2[BB][1024];          // 10-bit pass
__device__ int d_suff[FRB][1025];
__device__ int d_cgHi[FRB];
__device__ unsigned d_batchdone[BB];
__device__ unsigned d_done;
__device__ unsigned d_barctr[BB];

__device__ __nv_bfloat16 d_Xh[M_TOT * DD];      // 4 MB
__device__ __nv_bfloat16 d_Xl[M_TOT * DD];      // 4 MB
__device__ __nv_bfloat16 d_Wth[2][HH * DD];     // W^T hi, [n,k]
__device__ __nv_bfloat16 d_Wtl[2][HH * DD];     // W^T lo, [n,k]

// ======================= helpers ============================
__device__ __forceinline__ uint32_t smem_u32(const void* p)
{
    uint32_t a;
    asm("{ .reg .u64 t; cvta.to.shared.u64 t, %1; cvt.u32.u64 %0, t; }"
        : "=r"(a) : "l"(p));
    return a;
}

#define LDSM_X4(r0, r1, r2, r3, addr) \
    asm volatile("ldmatrix.sync.aligned.m8n8.x4.shared.b16 {%0,%1,%2,%3}, [%4];" \
                 : "=r"(r0), "=r"(r1), "=r"(r2), "=r"(r3) : "r"(addr))

#define MMA16816(d, a0, a1, a2, a3, b0, b1) \
    asm volatile("mma.sync.aligned.m16n8k16.row.col.f32.bf16.bf16.f32 " \
                 "{%0,%1,%2,%3}, {%4,%5,%6,%7}, {%8,%9}, {%0,%1,%2,%3};" \
                 : "+f"((d)[0]), "+f"((d)[1]), "+f"((d)[2]), "+f"((d)[3]) \
                 : "r"(a0), "r"(a1), "r"(a2), "r"(a3), "r"(b0), "r"(b1))

#define CP_ASYNC16(saddr, gaddr) \
    asm volatile("cp.async.cg.shared.global [%0], [%1], 16;" \
                 :: "r"(saddr), "l"(gaddr))
#define CP_COMMIT()  asm volatile("cp.async.commit_group;" ::: "memory")
#define CP_WAIT1()   asm volatile("cp.async.wait_group 1;" ::: "memory")
#define CP_WAIT0()   asm volatile("cp.async.wait_group 0;" ::: "memory")

// packed f32x2 math (PTX ISA 8.6, sm_100+)
__device__ __forceinline__ unsigned long long add2(unsigned long long a,
                                                   unsigned long long b)
{
    unsigned long long r;
    asm("add.rn.f32x2 %0, %1, %2;" : "=l"(r) : "l"(a), "l"(b));
    return r;
}
__device__ __forceinline__ unsigned long long fma2(unsigned long long a,
                                                   unsigned long long b,
                                                   unsigned long long c)
{
    unsigned long long r;
    asm("fma.rn.f32x2 %0, %1, %2, %3;" : "=l"(r) : "l"(a), "l"(b), "l"(c));
    return r;
}
__device__ __forceinline__ unsigned long long relu2(unsigned long long v)
{
    float a, b;
    asm("mov.b64 {%0, %1}, %2;" : "=f"(a), "=f"(b) : "l"(v));
    a = fmaxf(a, 0.f);
    b = fmaxf(b, 0.f);
    unsigned long long r;
    asm("mov.b64 %0, {%1, %2};" : "=l"(r) : "f"(a), "f"(b));
    return r;
}
__device__ __forceinline__ float sum2(unsigned long long v)
{
    float a, b;
    asm("mov.b64 {%0, %1}, %2;" : "=f"(a), "=f"(b) : "l"(v));
    return a + b;
}

// per-batch software grid barrier — BOUNDED spin (latent bug => garbage,
// not a dead container).  32 blocks per batch, all co-resident.
__device__ __forceinline__ void batch_barrier(int b, unsigned target)
{
    __syncthreads();
    if (threadIdx.x == 0) {
        __threadfence();
        atomicAdd(&d_barctr[b], 1u);
        for (int it = 0; it < 10000000; it++) {
            if (*(volatile unsigned*)&d_barctr[b] >= target) break;
        }
        __threadfence();
    }
    __syncthreads();
}

// =================================================================
// Fused conversion: X split (blocks 0..2047) + W transpose/split
// + cross-launch state zeroing.
// =================================================================
__global__ void __launch_bounds__(256)
fused_convert_kernel(const float* __restrict__ X,
                     const float* __restrict__ Ws, const float* __restrict__ We)
{
    const int tid = threadIdx.x;
    if (blockIdx.x < 2048) {
        int i = blockIdx.x * 256 + tid;          // float4 index
        float4 v = ((const float4*)X)[i];
        __nv_bfloat16 h0 = __float2bfloat16_rn(v.x);
        __nv_bfloat16 h1 = __float2bfloat16_rn(v.y);
        __nv_bfloat16 h2 = __float2bfloat16_rn(v.z);
        __nv_bfloat16 h3 = __float2bfloat16_rn(v.w);
        __nv_bfloat16 l0 = __float2bfloat16_rn(v.x - __bfloat162float(h0));
        __nv_bfloat16 l1 = __float2bfloat16_rn(v.y - __bfloat162float(h1));
        __nv_bfloat16 l2 = __float2bfloat16_rn(v.z - __bfloat162float(h2));
        __nv_bfloat16 l3 = __float2bfloat16_rn(v.w - __bfloat162float(h3));
        ((__nv_bfloat162*)d_Xh)[2 * i]     = __nv_bfloat162(h0, h1);
        ((__nv_bfloat162*)d_Xh)[2 * i + 1] = __nv_bfloat162(h2, h3);
        ((__nv_bfloat162*)d_Xl)[2 * i]     = __nv_bfloat162(l0, l1);
        ((__nv_bfloat162*)d_Xl)[2 * i + 1] = __nv_bfloat162(l2, l3);
        return;
    }

    const int wb = blockIdx.x - 2048;            // 0..1023
    if (wb == 0) {
        unsigned* h0p = (unsigned*)d_hist0;
        unsigned* h1p = (unsigned*)d_hist1;
        unsigned* h2p = (unsigned*)d_hist2;
        for (int i = tid; i < BB * 2048; i += 256) { h0p[i] = 0u; h1p[i] = 0u; }
        for (int i = tid; i < BB * 1024; i += 256) h2p[i] = 0u;
        if (tid < BB) { d_batchdone[tid] = 0u; d_barctr[tid] = 0u; }
        if (tid == 0) d_done = 0u;
    }
    const int z = wb >> 9;                       // 0/1
    const int rem = wb & 511;
    const int n0 = (rem & 15) * 32;              // 16 n-tiles
    const int k0 = (rem >> 4) * 32;              // 32 k-tiles

    const float* W = z ? We : Ws;
    __nv_bfloat16* oh = d_Wth[z];
    __nv_bfloat16* ol = d_Wtl[z];

    __shared__ float s[32][33];
    const int tx = tid & 31, ty = tid >> 5;      // 32x8

    for (int j = ty; j < 32; j += 8)
        s[j][tx] = W[(size_t)(k0 + j) * HH + n0 + tx];
    __syncthreads();
    for (int j = ty; j < 32; j += 8) {
        float v = s[tx][j];                      // W[k0+tx][n0+j]
        __nv_bfloat16 h = __float2bfloat16_rn(v);
        __nv_bfloat16 l = __float2bfloat16_rn(v - __bfloat162float(h));
        size_t o = (size_t)(n0 + j) * DD + k0 + tx;
        oh[o] = h;
        ol[o] = l;
    }
}

// =================================================================
// mma.sync GEMM: CTA tile 128x128, BK=64, 8 warps, cp.async 2-stage,
// 3-product bf16 split.  grid = (4, 16, 2), 256 threads.
// =================================================================
#define SKW_B 144                        // smem row stride bytes
#define BUF_BYTES (128 * SKW_B)          // 18432
#define STAGE_BYTES (4 * BUF_BYTES)      // 73728
#define GEMM_SMEM (2 * STAGE_BYTES)      // 147456

__global__ void __launch_bounds__(256, 1)
gemm_mma_kernel(const float* __restrict__ bias_s, const float* __restrict__ bias_e)
{
    extern __shared__ char smem[];
    const int tid = threadIdx.x, wid = tid >> 5, lane = tid & 31;
    const int which = blockIdx.z;
    const int m0 = blockIdx.y * 128, n0 = blockIdx.x * 128;

    const char* gsrc0[4];
    gsrc0[0] = (const char*)(d_Xh + (size_t)m0 * DD);
    gsrc0[1] = (const char*)(d_Xl + (size_t)m0 * DD);
    gsrc0[2] = (const char*)(d_Wth[which] + (size_t)n0 * DD);
    gsrc0[3] = (const char*)(d_Wtl[which] + (size_t)n0 * DD);

    const int lr = tid >> 3;             // 0..31 (row base; +32 per it)
    const int lc = tid & 7;              // 16B column 0..7

    const int warp_m = wid & 3, warp_n = wid >> 2;
    const int aRowOff = (warp_m * 32 + (lane & 15)) * SKW_B;
    const int aColOff = (lane >> 4) * 16;
    const int bRowOff = (warp_n * 64 + (lane & 7) + ((lane >> 4) << 3)) * SKW_B;
    const int bColOff = ((lane >> 3) & 1) * 16;

    float acc[2][8][4];
#pragma unroll
    for (int mt = 0; mt < 2; mt++)
#pragma unroll
        for (int nt = 0; nt < 8; nt++)
#pragma unroll
            for (int q = 0; q < 4; q++) acc[mt][nt][q] = 0.f;

    const uint32_t sstage[2] = { smem_u32(smem), smem_u32(smem + STAGE_BYTES) };

    #define ISSUE_STAGE(c, stg) do {                                          \
        const int kcB = (c) * 128;                                            \
        _Pragma("unroll")                                                     \
        for (int t = 0; t < 4; t++) {                                         \
            uint32_t sbase = sstage[stg] + t * BUF_BYTES;                     \
            const char* g = gsrc0[t] + kcB;                                   \
            _Pragma("unroll")                                                 \
            for (int it = 0; it < 4; it++) {                                  \
                int r = lr + it * 32;                                         \
                uint32_t sa = sbase + r * SKW_B + lc * 16;                    \
                const char* ga = g + (size_t)r * (DD * 2) + lc * 16;          \
                CP_ASYNC16(sa, ga);                                           \
            }                                                                 \
        }                                                                     \
        CP_COMMIT();                                                          \
    } while (0)

    ISSUE_STAGE(0, 0);

    const int pa[3] = {0, 0, 1};
    const int pb[3] = {2, 3, 2};

    for (int c = 0; c < 16; c++) {
        const int stg = c & 1;
        if (c + 1 < 16) { ISSUE_STAGE(c + 1, stg ^ 1); CP_WAIT1(); }
        else            { CP_WAIT0(); }
        __syncthreads();

        const uint32_t sb = sstage[stg];
#pragma unroll
        for (int kk = 0; kk < 4; kk++) {
#pragma unroll
            for (int p = 0; p < 3; p++) {
                const uint32_t ab = sb + pa[p] * BUF_BYTES + aRowOff + kk * 32 + aColOff;
                uint32_t a0[4], a1[4];
                LDSM_X4(a0[0], a0[1], a0[2], a0[3], ab);
                LDSM_X4(a1[0], a1[1], a1[2], a1[3], ab + 16 * SKW_B);

                const uint32_t bbase = sb + pb[p] * BUF_BYTES + bRowOff + kk * 32 + bColOff;
                uint32_t b[4][4];
#pragma unroll
                for (int ntp = 0; ntp < 4; ntp++)
                    LDSM_X4(b[ntp][0], b[ntp][1], b[ntp][2], b[ntp][3],
                            bbase + ntp * 16 * SKW_B);

#pragma unroll
                for (int nt = 0; nt < 8; nt++) {
                    const uint32_t bb0 = b[nt >> 1][(nt & 1) * 2];
                    const uint32_t bb1 = b[nt >> 1][(nt & 1) * 2 + 1];
                    MMA16816(acc[0][nt], a0[0], a0[1], a0[2], a0[3], bb0, bb1);
                    MMA16816(acc[1][nt], a1[0], a1[1], a1[2], a1[3], bb0, bb1);
                }
            }
        }
        __syncthreads();
    }

    const float* bias = which ? bias_e : bias_s;
    float* C = which ? d_he : d_hs;
    const int row0 = m0 + warp_m * 32 + (lane >> 2);
    const int col0 = n0 + warp_n * 64 + (lane & 3) * 2;
#pragma unroll
    for (int mt = 0; mt < 2; mt++) {
#pragma unroll
        for (int nt = 0; nt < 8; nt++) {
            const int row = row0 + mt * 16;
            const int col = col0 + nt * 8;
            const float b0 = bias[col], b1 = bias[col + 1];
            float2 v0 = { acc[mt][nt][0] + b0, acc[mt][nt][1] + b1 };
            float2 v1 = { acc[mt][nt][2] + b0, acc[mt][nt][3] + b1 };
            *(float2*)&C[(size_t)row * HH + col] = v0;
            *(float2*)&C[(size_t)(row + 8) * HH + col] = v1;
        }
    }
}

// =================================================================
// Fused span scoring + key emission + 11-bit histogram pass 0.
// grid = (36 tiles, 8 batches), 256 threads, 2x2/thread.
// Packed f32x2 inner loop: 8 math issues per span per 4 channels.
// =================================================================
__device__ __forceinline__ unsigned fkey(float f)
{
    unsigned u = __float_as_uint(f);
    return (u & 0x80000000u) ? ~u : (u | 0x80000000u);
}
__device__ __forceinline__ float fkey_inv(unsigned k)
{
    unsigned u = (k & 0x80000000u) ? (k & 0x7FFFFFFFu) : ~k;
    return __uint_as_float(u);
}

__device__ __forceinline__ void tile_decode32(int bx, int& ti, int& tj)
{
    int rem = bx;
    for (int r = 0; r < 8; r++) {
        int cnt = 8 - r;
        if (rem < cnt) { ti = r; tj = r + rem; return; }
        rem -= cnt;
    }
    ti = 0; tj = 0;
}

__global__ void __launch_bounds__(256)
score_kernel(const int* __restrict__ input_mask,
             const float* __restrict__ w_score,
             const float* __restrict__ b_score)
{
    const int b = blockIdx.y;
    int ti, tj;
    tile_decode32(blockIdx.x, ti, tj);

    __shared__ float hsS[32][132];
    __shared__ float heS[32][132];
    __shared__ float wS[128];
    __shared__ unsigned hloc[2048];

    const int i0 = ti * 32, j0 = tj * 32;
    const int tid = threadIdx.x;
    const int x = tid & 15, y = tid >> 4;

#pragma unroll
    for (int q = 0; q < 8; q++) hloc[tid + q * 256] = 0u;

    const float* hsBase = d_hs + ((size_t)b * TT + i0) * HH;
    const float* heBase = d_he + ((size_t)b * TT + j0) * HH;

    ulonglong2 A00 = {0ull, 0ull}, A01 = {0ull, 0ull};
    ulonglong2 A10 = {0ull, 0ull}, A11 = {0ull, 0ull};

    for (int ch = 0; ch < HH; ch += 128) {
        __syncthreads();
        if (tid < 32)
            *(float4*)&wS[tid * 4] = *(const float4*)&w_score[ch + tid * 4];
#pragma unroll
        for (int q = 0; q < 4; q++) {
            int idx = tid + q * 256;
            int r = idx >> 5;
            int c4 = (idx & 31) * 4;
            *(float4*)&hsS[r][c4] = *(const float4*)&hsBase[(size_t)r * HH + ch + c4];
            *(float4*)&heS[r][c4] = *(const float4*)&heBase[(size_t)r * HH + ch + c4];
        }
        __syncthreads();

#pragma unroll 4
        for (int c = 0; c < 128; c += 4) {
            ulonglong2 w2 = *(const ulonglong2*)&wS[c];
            ulonglong2 hA = *(const ulonglong2*)&hsS[y][c];
            ulonglong2 hB = *(const ulonglong2*)&hsS[y + 16][c];
            ulonglong2 eA = *(const ulonglong2*)&heS[x][c];
            ulonglong2 eB = *(const ulonglong2*)&heS[x + 16][c];
            A00.x = fma2(relu2(add2(hA.x, eA.x)), w2.x, A00.x);
            A00.y = fma2(relu2(add2(hA.y, eA.y)), w2.y, A00.y);
            A01.x = fma2(relu2(add2(hA.x, eB.x)), w2.x, A01.x);
            A01.y = fma2(relu2(add2(hA.y, eB.y)), w2.y, A01.y);
            A10.x = fma2(relu2(add2(hB.x, eA.x)), w2.x, A10.x);
            A10.y = fma2(relu2(add2(hB.y, eA.y)), w2.y, A10.y);
            A11.x = fma2(relu2(add2(hB.x, eB.x)), w2.x, A11.x);
            A11.y = fma2(relu2(add2(hB.y, eB.y)), w2.y, A11.y);
        }
    }

    const float acc00 = sum2(A00.x) + sum2(A00.y);
    const float acc01 = sum2(A01.x) + sum2(A01.y);
    const float acc10 = sum2(A10.x) + sum2(A10.y);
    const float acc11 = sum2(A11.x) + sum2(A11.y);

    const float bsc = *b_score;
    const int iA = i0 + y, iB = i0 + y + 16;
    const int jA = j0 + x, jB = j0 + x + 16;

    const int* mb = input_mask + b * TT;
    unsigned* kb = d_keys + (size_t)b * SS;

    #define EMITK(ii, jj, av)                                                 \
        if ((jj) >= (ii)) {                                                   \
            int s = (2 * (ii) * TT - (ii) * (ii) + (ii)) / 2 + ((jj) - (ii)); \
            bool ok = mb[(ii)] && mb[(jj)];                                   \
            float sv = ok ? ((av) + bsc) : NEGF;                              \
            unsigned k = fkey(sv);                                            \
            kb[s] = k;                                                        \
            atomicAdd(&hloc[k >> 21], 1u);                                    \
        }
    EMITK(iA, jA, acc00)
    EMITK(iA, jB, acc01)
    EMITK(iB, jA, acc10)
    EMITK(iB, jB, acc11)
    #undef EMITK

    __syncthreads();
#pragma unroll
    for (int q = 0; q < 8; q++) {
        int i = tid + q * 256;
        if (hloc[i]) atomicAdd(&d_hist0[b][i], hloc[i]);
    }
}

// =================================================================
// Tail: 11/11/10-digit radix select with 2 barriers + select +
// ticket finalize.  256 blocks x 256 threads.
// =================================================================
__device__ void fold_n(const unsigned* g, int nb, int shift,
                       unsigned& prefix, unsigned& R,
                       unsigned* sh, unsigned* shv)
{
    const int t = threadIdx.x;
    const int C = nb >> 8;               // 8 or 4
    unsigned v[8];
    unsigned tot = 0;
    for (int c = 0; c < C; c++) { v[c] = g[t * C + c]; tot += v[c]; }
    sh[t] = tot;
    __syncthreads();
    for (int off = 1; off < 256; off <<= 1) {
        unsigned add = (t + off < 256) ? sh[t + off] : 0u;
        __syncthreads();
        sh[t] += add;
        __syncthreads();
    }
    unsigned run = (t < 255) ? sh[t + 1] : 0u;   // suffix above my chunk
    for (int c = C - 1; c >= 0; c--) {
        unsigned sn = run;
        run += v[c];
        if (run >= R && sn < R) { shv[0] = (unsigned)(t * C + c); shv[1] = R - sn; }
    }
    __syncthreads();
    prefix |= shv[0] << (unsigned)shift;
    R = shv[1];
    __syncthreads();
}

__global__ void __launch_bounds__(256)
tail_kernel(const int* __restrict__ answer_spans, float* __restrict__ out)
{
    const int blk = blockIdx.x;          // 0..255
    const int b = blk >> 5, slice = blk & 31;
    const int t = threadIdx.x;
    const int w = t >> 5, lane = t & 31;
    const int s0 = slice * SLICE;
    const unsigned* kb = d_keys + (size_t)b * SS;

    __shared__ unsigned sh[256];
    __shared__ unsigned shv[2];
    __shared__ unsigned hloc[2048];
    __shared__ float redf[256];
    __shared__ int wcnt[8], ecnt[8];
    __shared__ int gold[NUM_GOLD];
    __shared__ int scgHi;
    __shared__ int sh_last;

    // ---- fold 0 (11 bits from score) ----
    unsigned prefix = 0u, R = K_TOP;
    fold_n(d_hist0[b], 2048, 21, prefix, R, sh, shv);
    const unsigned p11 = prefix >> 21;

    // ---- scan 1: filter top-11, histogram next 11 bits ----
#pragma unroll
    for (int q = 0; q < 8; q++) hloc[t + q * 256] = 0u;
    __syncthreads();
    for (int q = t; q < SLICE; q += 256) {
        unsigned u = kb[s0 + q];
        if ((u >> 21) == p11)
            atomicAdd(&hloc[(u >> 10) & 0x7FFu], 1u);
    }
    __syncthreads();
#pragma unroll
    for (int q = 0; q < 8; q++) {
        int i = t + q * 256;
        if (hloc[i]) atomicAdd(&d_hist1[b][i], hloc[i]);
    }
    batch_barrier(b, 32u);

    // ---- fold 1, then scan 2: last 10 bits + cgHi + suffix pub ----
    fold_n(d_hist1[b], 2048, 10, prefix, R, sh, shv);
    const unsigned p22 = prefix >> 10;

#pragma unroll
    for (int q = 0; q < 4; q++) hloc[t + q * 256] = 0u;
    if (t == 0) scgHi = 0;
    __syncthreads();
    {
        int cgHi = 0;
        for (int q = t; q < SLICE; q += 256) {
            unsigned u = kb[s0 + q];
            unsigned hi = u >> 10;
            if (hi == p22) atomicAdd(&hloc[u & 0x3FFu], 1u);
            else if (hi > p22) cgHi++;
        }
        if (cgHi) atomicAdd(&scgHi, cgHi);
    }
    __syncthreads();
    // publish local suffix sums of the 1024-bin hloc, then merge global
    {
        unsigned v[4];
        unsigned tot = 0;
#pragma unroll
        for (int c = 0; c < 4; c++) { v[c] = hloc[t * 4 + c]; tot += v[c]; }
        sh[t] = tot;
        __syncthreads();
        for (int off = 1; off < 256; off <<= 1) {
            unsigned add = (t + off < 256) ? sh[t + off] : 0u;
            __syncthreads();
            sh[t] += add;
            __syncthreads();
        }
        unsigned run = (t < 255) ? sh[t + 1] : 0u;
#pragma unroll
        for (int c = 3; c >= 0; c--) {
            run += v[c];
            d_suff[blk][t * 4 + c] = (int)run;
        }
        if (t == 0) { d_suff[blk][1024] = 0; d_cgHi[blk] = scgHi; }
#pragma unroll
        for (int c = 0; c < 4; c++)
            if (v[c]) atomicAdd(&d_hist2[b][t * 4 + c], v[c]);
    }
    batch_barrier(b, 64u);

    // ---- fold 2 -> exact threshold ----
    fold_n(d_hist2[b], 1024, 0, prefix, R, sh, shv);
    const unsigned thresh = prefix;
    const int numEq = (int)R;
    const int dstar = (int)(thresh & 0x3FFu);

    // ---- select: ordered positioned writes ----
    {
        int rg = 0, re = 0;
        for (int sl = 0; sl < slice; sl++) {
            int bb = (b << 5) + sl;
            int sA = d_suff[bb][dstar];
            int sB = d_suff[bb][dstar + 1];
            rg += d_cgHi[bb] + sB;
            re += sA - sB;
        }
        const unsigned lt = (1u << lane) - 1u;
        for (int c0 = 0; c0 < SLICE; c0 += 256) {
            int q = c0 + t;
            bool valid = q < SLICE;
            unsigned u = valid ? kb[s0 + q] : 0u;
            bool g = valid && (u > thresh);
            bool e = valid && (u == thresh);
            unsigned bg = __ballot_sync(0xffffffffu, g);
            unsigned be = __ballot_sync(0xffffffffu, e);
            if (lane == 0) { wcnt[w] = __popc(bg); ecnt[w] = __popc(be); }
            __syncthreads();
            int exg = 0, exe = 0, tg = 0, te = 0;
#pragma unroll
            for (int ww = 0; ww < 8; ww++) {
                if (ww < w) { exg += wcnt[ww]; exe += ecnt[ww]; }
                tg += wcnt[ww]; te += ecnt[ww];
            }
            if (g || e) {
                int mg = __popc(bg & lt), me = __popc(be & lt);
                int gBefore = rg + exg + mg;
                int eBefore = re + exe + me;
                bool sel = g || (eBefore < numEq);
                int pos = gBefore + min(eBefore, numEq);
                if (sel && pos < K_TOP) {
                    d_topidx[b * K_TOP + pos] = s0 + q;
                    d_toplog[b * K_TOP + pos] = fkey_inv(u);
                }
            }
            __syncthreads();
            rg += tg; re += te;
        }
    }

    // ---- per-batch finalize ticket: last block of batch finalizes ----
    __syncthreads();
    if (t == 0) {
        __threadfence();
        unsigned v = atomicAdd(&d_batchdone[b], 1u);
        sh_last = (v == 31u) ? 1 : 0;
    }
    __syncthreads();

    if (sh_last) {
        __threadfence();
        if (t < NUM_GOLD) {
            int g0 = answer_spans[(b * NUM_GOLD + t) * 2 + 0];
            int e0 = answer_spans[(b * NUM_GOLD + t) * 2 + 1];
            int idx = (2 * g0 * TT - g0 * g0 + g0) / 2 + (e0 - g0);
            gold[t] = (g0 >= 0) ? idx : -1;
        }
        __syncthreads();
        float lsum = 0.f;
#pragma unroll
        for (int r2 = 0; r2 < 2; r2++) {
            int k = t + r2 * 256;
            int sIdx = d_topidx[b * K_TOP + k];
            float l = d_toplog[b * K_TOP + k];
            float m = (l > -1e19f) ? 1.f : 0.f;
            float pred = 0.f;
#pragma unroll
            for (int g2 = 0; g2 < NUM_GOLD; g2++)
                if (gold[g2] == sIdx) pred = 1.f;
            out[b * K_TOP + k] = (1.f / (1.f + expf(-l))) * m;
            lsum += m * (fmaxf(l, 0.f) - l * pred + log1pf(expf(-fabsf(l))));
        }
        redf[t] = lsum;
        __syncthreads();
        for (int st = 128; st > 0; st >>= 1) {
            if (t < st) redf[t] += redf[t + st];
            __syncthreads();
        }
        if (t == 0) {
            d_losspart[b] = redf[0];
            d_batchdone[b] = 0u;          // reset for next replay
            d_barctr[b] = 0u;             // reset per-batch barrier
            __threadfence();
            unsigned v = atomicAdd(&d_done, 1u);
            if (v == BB - 1) {
                float ssum = 0.f;
                for (int q2 = 0; q2 < BB; q2++) ssum += d_losspart[q2];
                out[BB * K_TOP] = ssum;
                d_done = 0u;
            }
        }
    }
}

// =================================================================
// Launch — 4 graph nodes
// =================================================================
extern "C" void kernel_launch(void* const* d_in, const int* in_sizes, int n_in,
                              void* d_out, int out_size)
{
    const float* inputs       = (const float*)d_in[0];
    const int*   input_mask   = (const int*)d_in[1];
    const int*   answer_spans = (const int*)d_in[2];
    const float* W_start      = (const float*)d_in[3];
    const float* b_start      = (const float*)d_in[4];
    const float* W_end        = (const float*)d_in[5];
    const float* b_end        = (const float*)d_in[6];
    const float* w_score      = (const float*)d_in[7];
    const float* b_score      = (const float*)d_in[8];
    float* out = (float*)d_out;

    static int smem_set = 0;
    if (!smem_set) {
        cudaFuncSetAttribute(gemm_mma_kernel,
                             cudaFuncAttributeMaxDynamicSharedMemorySize, GEMM_SMEM);
        smem_set = 1;
    }

    fused_convert_kernel<<<3072, 256>>>(inputs, W_start, W_end);

    dim3 gGemm(HH / 128, M_TOT / 128, 2);   // (4, 16, 2)
    gemm_mma_kernel<<<gGemm, 256, GEMM_SMEM>>>(b_start, b_end);

    dim3 gScore(36, BB);
    score_kernel<<<gScore, 256>>>(input_mask, w_score, b_score);

    tail_kernel<<<FRB, 256>>>(answer_spans, out);
}